// round 12
// baseline (speedup 1.0000x reference)
#include <cuda_runtime.h>
#include <cstdint>

#define N_NODES 100000
#define N_EDGES 6400000
#define MIN_DIST 5.0f
#define CNT_OFFSET 512.0f

#define CLUSTER 8
#define NODES_PER_CTA 12500          // 12500 * 16 B = 200 000 B smem per CTA
#define SMEM_BYTES (NODES_PER_CTA * 16)
#define BLOCK 512
#define GRID 144                     // 18 clusters of 8; 1 CTA/SM wave

// Per-node 16B accumulator: {cx_sum + 512*cnt, cy_sum, mx_sum, my_sum}
// |sum(cx)| <= cnt <= ~120 < 256, so cnt = rint(x/512) is exact.
// Zero-initialized at module load; finalize re-zeros after reading.
__device__ __align__(16) float4 g_acc[N_NODES];

__device__ __forceinline__ float4 dsmem_gather(uint32_t smem_base, uint32_t idx) {
    uint32_t rank = idx / (uint32_t)NODES_PER_CTA;            // 0..7
    uint32_t off  = idx - rank * (uint32_t)NODES_PER_CTA;
    uint32_t laddr = smem_base + off * 16u;
    uint32_t raddr;
    asm("mapa.shared::cluster.u32 %0, %1, %2;" : "=r"(raddr) : "r"(laddr), "r"(rank));
    float4 v;
    asm volatile("ld.shared::cluster.v4.f32 {%0,%1,%2,%3}, [%4];"
                 : "=f"(v.x), "=f"(v.y), "=f"(v.z), "=f"(v.w)
                 : "r"(raddr));
    return v;
}

__global__ void __launch_bounds__(BLOCK, 1) __cluster_dims__(CLUSTER, 1, 1)
edge_cluster_kernel(const float2* __restrict__ pos,
                    const float2* __restrict__ vel,
                    const int4* __restrict__ src4,
                    const int4* __restrict__ dst4) {
    extern __shared__ float4 sh[];   // this CTA's 12500-node slice of h
    uint32_t smem_base;
    asm("{ .reg .u64 t; cvta.to.shared.u64 t, %1; cvt.u32.u64 %0, t; }"
        : "=r"(smem_base) : "l"(sh));

    uint32_t rank;
    asm("mov.u32 %0, %%cluster_ctarank;" : "=r"(rank));

    // Stage phase: this CTA owns nodes [rank*12500, (rank+1)*12500).
    int base = (int)rank * NODES_PER_CTA;
    for (int j = threadIdx.x; j < NODES_PER_CTA; j += BLOCK) {
        float2 p = __ldg(&pos[base + j]);
        float2 v = __ldg(&vel[base + j]);
        sh[j] = make_float4(p.x, p.y, v.x, v.y);
    }

    // All 8 CTAs' smem slices must be complete before any DSMEM gather.
    asm volatile("barrier.cluster.arrive.aligned;" ::: "memory");
    asm volatile("barrier.cluster.wait.aligned;" ::: "memory");

    int stride = GRID * BLOCK;
    for (int t = blockIdx.x * BLOCK + threadIdx.x; t < N_EDGES / 4; t += stride) {
        int4 s4 = __ldg(&src4[t]);
        int4 d4 = __ldg(&dst4[t]);

        uint32_t s[4] = {(uint32_t)s4.x, (uint32_t)s4.y, (uint32_t)s4.z, (uint32_t)s4.w};
        uint32_t d[4] = {(uint32_t)d4.x, (uint32_t)d4.y, (uint32_t)d4.z, (uint32_t)d4.w};

        // Batch 8 independent DSMEM gathers for latency hiding.
        float4 hs[4], hd[4];
#pragma unroll
        for (int k = 0; k < 4; k++) hs[k] = dsmem_gather(smem_base, s[k]);
#pragma unroll
        for (int k = 0; k < 4; k++) hd[k] = dsmem_gather(smem_base, d[k]);

#pragma unroll
        for (int k = 0; k < 4; k++) {
            float dx = hs[k].x - hd[k].x;
            float dy = hs[k].y - hd[k].y;
            float n2 = dx * dx + dy * dy;

            float rn = (n2 > 0.f) ? rsqrtf(n2) : 0.f;
            float norm = n2 * rn;

            // sigmoid(-10*(norm-5)) = 1/(1+exp(10*(norm-5)))
            float sig = 1.f / (1.f + __expf(10.f * (norm - MIN_DIST)));
            float kk = -sig * rn;
            float cx = kk * dx;
            float cy = kk * dy;

            float mx = dx * (1.f / 30.f) + (hs[k].z - hd[k].z);
            float my = dy * (1.f / 30.f) + (hs[k].w - hd[k].w);

            asm volatile("red.global.add.v4.f32 [%0], {%1, %2, %3, %4};"
                         :: "l"(&g_acc[d[k]]),
                            "f"(cx + CNT_OFFSET), "f"(cy), "f"(mx), "f"(my)
                         : "memory");
        }
    }

    // No CTA may exit while cluster peers can still read its smem.
    asm volatile("barrier.cluster.arrive.aligned;" ::: "memory");
    asm volatile("barrier.cluster.wait.aligned;" ::: "memory");
}

__global__ void finalize_kernel(float2* __restrict__ out) {
    int i = blockIdx.x * blockDim.x + threadIdx.x;
    if (i < N_NODES) {
        float4 a = g_acc[i];
        // Re-zero for the next replay (line is hot; store is nearly free).
        g_acc[i] = make_float4(0.f, 0.f, 0.f, 0.f);
        float cnt = rintf(a.x * (1.0f / CNT_OFFSET));
        float sum_cx = a.x - cnt * CNT_OFFSET;
        float inv = 1.0f / fmaxf(cnt, 1.0f);
        float2 o;
        o.x = sum_cx * 5.0f + a.z * inv;
        o.y = a.y    * 5.0f + a.w * inv;
        out[i] = o;
    }
}

extern "C" void kernel_launch(void* const* d_in, const int* in_sizes, int n_in,
                              void* d_out, int out_size) {
    const float2* pos = (const float2*)d_in[0];
    const float2* vel = (const float2*)d_in[1];
    const int* edge = (const int*)d_in[2];
    const int4* src4 = (const int4*)edge;
    const int4* dst4 = (const int4*)(edge + N_EDGES);
    float2* out = (float2*)d_out;

    // Idempotent, not a stream op: opt in to >48KB dynamic smem.
    cudaFuncSetAttribute(edge_cluster_kernel,
                         cudaFuncAttributeMaxDynamicSharedMemorySize, SMEM_BYTES);

    edge_cluster_kernel<<<GRID, BLOCK, SMEM_BYTES>>>(pos, vel, src4, dst4);

    {
        int threads = 256;
        int blocks = (N_NODES + threads - 1) / threads;
        finalize_kernel<<<blocks, threads>>>(out);
    }
}

// round 14
// speedup vs baseline: 3.4324x; 3.4324x over previous
#include <cuda_runtime.h>
#include <cstdint>

#define N_NODES 100000
#define N_EDGES 6400000
#define MIN_DIST 5.0f
#define CNT_OFFSET 512.0f

// Per-node 16B accumulator: {cx_sum + 512*cnt, cy_sum, mx_sum, my_sum}
// |sum(cx)| <= cnt <= ~120 < 256, so cnt = rint(x/512) is exact.
// Zero-initialized at module load; finalize re-zeros after reading so the
// invariant (acc==0 before each edge pass) holds for every graph replay.
__device__ __align__(16) float4 g_acc[N_NODES];
__device__ float4 g_h[N_NODES];     // {pos.x, pos.y, vel.x, vel.y}

// Prep: build packed h array only.
__global__ void prep_kernel(const float2* __restrict__ pos,
                            const float2* __restrict__ vel) {
    int i = blockIdx.x * blockDim.x + threadIdx.x;
    if (i < N_NODES) {
        float2 p = pos[i];
        float2 v = vel[i];
        g_h[i] = make_float4(p.x, p.y, v.x, v.y);
    }
}

__global__ void __launch_bounds__(256) edge_kernel(const int4* __restrict__ src4,
                                                   const int4* __restrict__ dst4) {
    int t = blockIdx.x * blockDim.x + threadIdx.x;
    if (t >= N_EDGES / 4) return;

    int4 s4 = __ldg(&src4[t]);
    int4 d4 = __ldg(&dst4[t]);

    int s[4] = {s4.x, s4.y, s4.z, s4.w};
    int d[4] = {d4.x, d4.y, d4.z, d4.w};

    // Batch all 8 gathers up front for MLP (32 regs of gather data: no spills).
    float4 hs[4], hd[4];
#pragma unroll
    for (int k = 0; k < 4; k++) hs[k] = g_h[s[k]];
#pragma unroll
    for (int k = 0; k < 4; k++) hd[k] = g_h[d[k]];

#pragma unroll
    for (int k = 0; k < 4; k++) {
        float dx = hs[k].x - hd[k].x;
        float dy = hs[k].y - hd[k].y;
        float n2 = dx * dx + dy * dy;

        // rn = 1/norm (0 if norm==0, handles self-edges branchlessly)
        float rn = (n2 > 0.f) ? rsqrtf(n2) : 0.f;
        float norm = n2 * rn;

        // sigmoid(-10*(norm-5)) = 1/(1+exp(10*(norm-5)))
        float sig = 1.f / (1.f + __expf(10.f * (norm - MIN_DIST)));
        float kk = -sig * rn;
        float cx = kk * dx;
        float cy = kk * dy;

        float mx = dx * (1.f / 30.f) + (hs[k].z - hd[k].z);
        float my = dy * (1.f / 30.f) + (hs[k].w - hd[k].w);

        // Single 16B reduction per edge; count encoded as +512 in lane x.
        asm volatile("red.global.add.v4.f32 [%0], {%1, %2, %3, %4};"
                     :: "l"(&g_acc[d[k]]),
                        "f"(cx + CNT_OFFSET), "f"(cy), "f"(mx), "f"(my)
                     : "memory");
    }
}

__global__ void finalize_kernel(float2* __restrict__ out) {
    int i = blockIdx.x * blockDim.x + threadIdx.x;
    if (i < N_NODES) {
        float4 a = g_acc[i];
        // Re-zero for the next replay (line is hot; store is nearly free).
        g_acc[i] = make_float4(0.f, 0.f, 0.f, 0.f);
        float cnt = rintf(a.x * (1.0f / CNT_OFFSET));
        float sum_cx = a.x - cnt * CNT_OFFSET;
        float inv = 1.0f / fmaxf(cnt, 1.0f);
        float2 o;
        o.x = sum_cx * 5.0f + a.z * inv;
        o.y = a.y    * 5.0f + a.w * inv;
        out[i] = o;
    }
}

extern "C" void kernel_launch(void* const* d_in, const int* in_sizes, int n_in,
                              void* d_out, int out_size) {
    const float2* pos = (const float2*)d_in[0];
    const float2* vel = (const float2*)d_in[1];
    const int* edge = (const int*)d_in[2];
    const int4* src4 = (const int4*)edge;
    const int4* dst4 = (const int4*)(edge + N_EDGES);
    float2* out = (float2*)d_out;

    {
        int threads = 256;
        int blocks = (N_NODES + threads - 1) / threads;
        prep_kernel<<<blocks, threads>>>(pos, vel);
    }
    {
        int threads = 256;
        int nthreads = N_EDGES / 4;
        int blocks = (nthreads + threads - 1) / threads;
        edge_kernel<<<blocks, threads>>>(src4, dst4);
    }
    {
        int threads = 256;
        int blocks = (N_NODES + threads - 1) / threads;
        finalize_kernel<<<blocks, threads>>>(out);
    }
}

// round 15
// speedup vs baseline: 3.5245x; 1.0269x over previous
#include <cuda_runtime.h>
#include <cstdint>

#define N_NODES 100000
#define N_EDGES 6400000
#define MIN_DIST 5.0f
#define CNT_OFFSET 512.0f

// Per-node 16B accumulator: {cx_sum + 512*cnt, cy_sum, mx_sum, my_sum}
// |sum(cx)| <= cnt <= ~120 < 256, so cnt = rint(x/512) is exact.
// prep zeroes g_acc on every call (graph replay safe); finalize is read-only.
__device__ __align__(16) float4 g_acc[N_NODES];
__device__ float4 g_h[N_NODES];     // {pos.x, pos.y, vel.x, vel.y}

// Fused prep: zero accumulators + build packed h array.
__global__ void prep_kernel(const float2* __restrict__ pos,
                            const float2* __restrict__ vel) {
    int i = blockIdx.x * blockDim.x + threadIdx.x;
    if (i < N_NODES) {
        g_acc[i] = make_float4(0.f, 0.f, 0.f, 0.f);
        float2 p = pos[i];
        float2 v = vel[i];
        g_h[i] = make_float4(p.x, p.y, v.x, v.y);
    }
}

__global__ void __launch_bounds__(256) edge_kernel(const int4* __restrict__ src4,
                                                   const int4* __restrict__ dst4) {
    int t = blockIdx.x * blockDim.x + threadIdx.x;
    if (t >= N_EDGES / 4) return;

    int4 s4 = __ldg(&src4[t]);
    int4 d4 = __ldg(&dst4[t]);

    int s[4] = {s4.x, s4.y, s4.z, s4.w};
    int d[4] = {d4.x, d4.y, d4.z, d4.w};

    // Batch all 8 gathers up front for MLP (32 regs of gather data: no spills).
    float4 hs[4], hd[4];
#pragma unroll
    for (int k = 0; k < 4; k++) hs[k] = g_h[s[k]];
#pragma unroll
    for (int k = 0; k < 4; k++) hd[k] = g_h[d[k]];

#pragma unroll
    for (int k = 0; k < 4; k++) {
        float dx = hs[k].x - hd[k].x;
        float dy = hs[k].y - hd[k].y;
        float n2 = dx * dx + dy * dy;

        // rn = 1/norm (0 if norm==0, handles self-edges branchlessly)
        float rn = (n2 > 0.f) ? rsqrtf(n2) : 0.f;
        float norm = n2 * rn;

        // sigmoid(-10*(norm-5)) = 1/(1+exp(10*(norm-5)))
        float sig = 1.f / (1.f + __expf(10.f * (norm - MIN_DIST)));
        float kk = -sig * rn;
        float cx = kk * dx;
        float cy = kk * dy;

        float mx = dx * (1.f / 30.f) + (hs[k].z - hd[k].z);
        float my = dy * (1.f / 30.f) + (hs[k].w - hd[k].w);

        // Single 16B reduction per edge; count encoded as +512 in lane x.
        asm volatile("red.global.add.v4.f32 [%0], {%1, %2, %3, %4};"
                     :: "l"(&g_acc[d[k]]),
                        "f"(cx + CNT_OFFSET), "f"(cy), "f"(mx), "f"(my)
                     : "memory");
    }
}

__global__ void finalize_kernel(float2* __restrict__ out) {
    int i = blockIdx.x * blockDim.x + threadIdx.x;
    if (i < N_NODES) {
        float4 a = g_acc[i];
        float cnt = rintf(a.x * (1.0f / CNT_OFFSET));
        float sum_cx = a.x - cnt * CNT_OFFSET;
        float inv = 1.0f / fmaxf(cnt, 1.0f);
        float2 o;
        o.x = sum_cx * 5.0f + a.z * inv;
        o.y = a.y    * 5.0f + a.w * inv;
        out[i] = o;
    }
}

extern "C" void kernel_launch(void* const* d_in, const int* in_sizes, int n_in,
                              void* d_out, int out_size) {
    const float2* pos = (const float2*)d_in[0];
    const float2* vel = (const float2*)d_in[1];
    const int* edge = (const int*)d_in[2];
    const int4* src4 = (const int4*)edge;
    const int4* dst4 = (const int4*)(edge + N_EDGES);
    float2* out = (float2*)d_out;

    {
        int threads = 256;
        int blocks = (N_NODES + threads - 1) / threads;
        prep_kernel<<<blocks, threads>>>(pos, vel);
    }
    {
        int threads = 256;
        int nthreads = N_EDGES / 4;
        int blocks = (nthreads + threads - 1) / threads;
        edge_kernel<<<blocks, threads>>>(src4, dst4);
    }
    {
        int threads = 256;
        int blocks = (N_NODES + threads - 1) / threads;
        finalize_kernel<<<blocks, threads>>>(out);
    }
}